// round 10
// baseline (speedup 1.0000x reference)
#include <cuda_runtime.h>

// Shape: [1, 8, 8, 8, 258, 258, 1] fp32; 512 images of 258x258.
// 34,080,768 elems = 8,520,192 float4 chunks; grid 33282 x 256 exact.
//
// Fully branchless single pass. Per chunk:
//   v = LDG.128 @ idx (always)
//   u = elements idx+D .. idx+D+3 via 2 predicated LDG.64 (8B-aligned),
//       D = +258 if chunk touches row 0, -258 if row 257 / straddle into 257.
//       Needed for only 1.6% of chunks (warp-uniform predicate -> no traffic
//       and no divergence elsewhere).
// Lane selects (258 % 4 == 2 puts w-edge sources in-chunk; w-rule wins at
// corners with ORIGINAL h; h-edge lanes read from u):
//   e0=(w0==0)  e4=(w0==254)  s=(w0==256)
//   top=(rem<258)  bot=(rem>=66306)  sb=(rem==66304)  tb=top|bot
//   lane0 = e0 ? v.y : tb ? u.x : v.x
//   lane1 = s  ? v.x : tb ? u.y : v.y
//   lane2 = s  ? v.w : tb ? u.z : v.z
//   lane3 = e4 ? v.z : (s ? sb : tb) ? u.w : v.w

#define HW        258u
#define IMG_ELEMS 66564u
#define TOTAL4    8520192u
#define ROW_BOT   66306u      // 257*258
#define SB_REM    66304u      // 256*258 + 256

__global__ __launch_bounds__(256)
void halo_bl_kernel(const float* __restrict__ x,
                    const float4* __restrict__ hm,
                    float4* __restrict__ out)
{
    unsigned i = blockIdx.x * 256u + threadIdx.x;   // exact cover
    unsigned idx = i * 4u;

    float4 v = __ldcs(reinterpret_cast<const float4*>(x + idx));
    float4 b = __ldcs(hm + i);

    unsigned rem = idx % IMG_ELEMS;
    unsigned w0  = rem % HW;            // even

    bool e0  = (w0 == 0u);
    bool e4  = (w0 == HW - 4u);         // 254
    bool s   = (w0 == HW - 2u);         // 256 (straddle)
    bool top = (rem < HW);
    bool bot = (rem >= ROW_BOT);
    bool sb  = (rem == SB_REM);         // straddle into row 257
    bool tb  = top | bot;

    float u0 = 0.f, u1 = 0.f, u2 = 0.f, u3 = 0.f;
    if (tb | sb) {                      // predicated 8B loads, 1.6% of chunks
        int D = top ? (int)HW : -(int)HW;
        const float* p = x + (int)idx + D;
        float2 ua = *reinterpret_cast<const float2*>(p);
        float2 ub = *reinterpret_cast<const float2*>(p + 2);
        u0 = ua.x; u1 = ua.y; u2 = ub.x; u3 = ub.y;
    }

    float a0 = e0 ? v.y : (tb ? u0 : v.x);
    float a1 = s  ? v.x : (tb ? u1 : v.y);
    float a2 = s  ? v.w : (tb ? u2 : v.z);
    float a3 = e4 ? v.z : ((s ? sb : tb) ? u3 : v.w);

    float4 r;
    r.x = a0 * b.x;
    r.y = a1 * b.y;
    r.z = a2 * b.z;
    r.w = a3 * b.w;
    __stcs(out + i, r);
}

extern "C" void kernel_launch(void* const* d_in, const int* in_sizes, int n_in,
                              void* d_out, int out_size)
{
    const float* x  = (const float*)d_in[0];
    const float* hm = (const float*)d_in[1];
    float* out = (float*)d_out;

    halo_bl_kernel<<<TOTAL4 / 256u, 256>>>(x, (const float4*)hm, (float4*)out);
}